// round 7
// baseline (speedup 1.0000x reference)
#include <cuda_runtime.h>
#include <math.h>

#define NN  4096
#define KK  32
#define DD  64
#define BSZ 8
#define TT  32
#define HSZ 256
#define TILE 64

typedef unsigned long long u64;

// ---------------- persistent device scratch (float4-aligned) ----------------
__device__ float4 g_wsig4[BSZ*NN*KK/4];
__device__ float  g_d[BSZ*NN];
__device__ float  g_dec[BSZ*NN];
__device__ float  g_prim[BSZ*NN*DD];
__device__ float4 g_sconst4[(size_t)BSZ*NN*HSZ/4];
__device__ float4 g_mconst4[(size_t)BSZ*NN*HSZ/4];
__device__ float4 g_h4[BSZ*NN*DD/4];
__device__ float4 g_msg4[2][BSZ*NN*DD/4];
__device__ float4 g_Wsi4[DD*HSZ/4];    // state_w1[:, :64]  -> [j][h]
__device__ float4 g_Ws24[HSZ*DD/4];    // state_w2          -> [h][o]
__device__ float4 g_Wmh4[DD*HSZ/4];    // msg_w1[:, :64]    -> [j][h]
__device__ float4 g_Wm24[HSZ*DD/4];    // msg_w2            -> [h][o]
__device__ float  g_WsC[129*HSZ];      // const-GEMM weights [j][h]
__device__ float  g_WmC[129*HSZ];

// ---------------- fast math + f32x2 helpers ----------------
__device__ __forceinline__ float ftanh(float x) {
    float ax = fabsf(x);
    float e  = __expf(-2.f*ax);
    float t  = __fdividef(1.f - e, 1.f + e);
    return copysignf(t, x);
}
__device__ __forceinline__ float fsigmoid(float x) {
    return __fdividef(1.f, 1.f + __expf(-x));
}
__device__ __forceinline__ u64 pack2(float x) {
    u64 r; unsigned xi = __float_as_uint(x);
    asm("mov.b64 %0, {%1,%1};" : "=l"(r) : "r"(xi));
    return r;
}
__device__ __forceinline__ float2 unpack2(u64 v) {
    unsigned lo, hi;
    asm("mov.b64 {%0,%1}, %2;" : "=r"(lo), "=r"(hi) : "l"(v));
    return make_float2(__uint_as_float(lo), __uint_as_float(hi));
}
__device__ __forceinline__ void ffma2(u64& d, u64 a, u64 b) {
    asm("fma.rn.f32x2 %0, %1, %2, %0;" : "+l"(d) : "l"(a), "l"(b));
}

// ---------------- init: copy state, pack weights ----------------
__global__ void k_init(const float* __restrict__ h_in, const float* __restrict__ msg_in,
                       const float* __restrict__ sw1, const float* __restrict__ sw2,
                       const float* __restrict__ mw1, const float* __restrict__ mw2)
{
    int i0 = blockIdx.x*blockDim.x + threadIdx.x;
    int stride = gridDim.x*blockDim.x;
    float* gh   = (float*)g_h4;
    float* gm0  = (float*)g_msg4[0];
    float* Wsi  = (float*)g_Wsi4;  float* Ws2 = (float*)g_Ws24;
    float* Wmh  = (float*)g_Wmh4;  float* Wm2 = (float*)g_Wm24;
    for (int i = i0; i < BSZ*NN*DD; i += stride) { gh[i] = h_in[i]; gm0[i] = msg_in[i]; }
    for (int i = i0; i < DD*HSZ; i += stride) {
        int j = i >> 8, h = i & 255;
        Wsi[i] = sw1[h*193 + j];
        Wmh[i] = mw1[h*192 + j];
    }
    for (int i = i0; i < HSZ*DD; i += stride) {
        int h = i >> 6, o = i & 63;
        Ws2[i] = sw2[o*256 + h];
        Wm2[i] = mw2[o*256 + h];
    }
    for (int i = i0; i < 129*HSZ; i += stride) {
        int j = i >> 8, h = i & 255;
        g_WsC[i] = (j < 128) ? sw1[h*193 + 64 + j] : sw1[h*193 + 192];
        g_WmC[i] = (j < 128) ? mw1[h*192 + 64 + j] : 0.f;
    }
}

// ---------------- per-neuron modulation MLP ----------------
__global__ void k_mod(const float* __restrict__ h_in, const float* __restrict__ heb,
                      const float* __restrict__ dec_in, const float* __restrict__ prim_in,
                      const float* __restrict__ wconn_in,
                      const float* __restrict__ mw1, const float* __restrict__ mb1,
                      const float* __restrict__ mw2, const float* __restrict__ mb2,
                      const float* __restrict__ nid)
{
    const int n = blockIdx.x;
    const int tid = threadIdx.x;
    const int warp = tid >> 5, lane = tid & 31;
    __shared__ float xs[BSZ*225];
    __shared__ float hid[BSZ*64];
    __shared__ float dlt[BSZ*97];

    for (int i = tid; i < BSZ*225; i += 256) {
        int b = i / 225, j = i - b*225;
        size_t bn = (size_t)b*NN + n;
        float v;
        if (j < 32)        v = heb[bn*32 + j];
        else if (j < 96)   v = h_in[bn*64 + (j-32)];
        else if (j == 96)  v = dec_in[bn];
        else if (j < 161)  v = prim_in[bn*64 + (j-97)];
        else               v = nid[(size_t)n*64 + (j-161)];
        xs[i] = v;
    }
    __syncthreads();

    const float* w1 = mw1 + (size_t)n*64*225;
    for (int hh = warp; hh < 64; hh += 8) {
        float acc[BSZ];
        #pragma unroll
        for (int b = 0; b < BSZ; b++) acc[b] = 0.f;
        for (int j = lane; j < 225; j += 32) {
            float w = w1[hh*225 + j];
            #pragma unroll
            for (int b = 0; b < BSZ; b++) acc[b] += w * xs[b*225 + j];
        }
        #pragma unroll
        for (int off = 16; off; off >>= 1) {
            #pragma unroll
            for (int b = 0; b < BSZ; b++) acc[b] += __shfl_xor_sync(0xffffffffu, acc[b], off);
        }
        if (lane == 0) {
            float bb = mb1[(size_t)n*64 + hh];
            #pragma unroll
            for (int b = 0; b < BSZ; b++) hid[b*64 + hh] = ftanh(acc[b] + bb);
        }
    }
    __syncthreads();

    const float* w2 = mw2 + (size_t)n*64*97;
    for (int o = warp; o < 97; o += 8) {
        float acc[BSZ];
        #pragma unroll
        for (int b = 0; b < BSZ; b++) acc[b] = 0.f;
        #pragma unroll
        for (int j2 = 0; j2 < 2; ++j2) {
            int j = lane + 32*j2;
            float w = w2[(size_t)j*97 + o];
            #pragma unroll
            for (int b = 0; b < BSZ; b++) acc[b] += w * hid[b*64 + j];
        }
        #pragma unroll
        for (int off = 16; off; off >>= 1) {
            #pragma unroll
            for (int b = 0; b < BSZ; b++) acc[b] += __shfl_xor_sync(0xffffffffu, acc[b], off);
        }
        if (lane == 0) {
            float bb = mb2[(size_t)n*97 + o];
            #pragma unroll
            for (int b = 0; b < BSZ; b++) dlt[b*97 + o] = acc[b] + bb;
        }
    }
    __syncthreads();

    float* wsig = (float*)g_wsig4;
    for (int i = tid; i < BSZ*KK; i += 256) {
        int b = i >> 5, k = i & 31;
        size_t bn = (size_t)b*NN + n;
        wsig[bn*32 + k] = fsigmoid(wconn_in[bn*32 + k] + dlt[b*97 + k]);
    }
    if (tid < BSZ) {
        size_t bn = (size_t)tid*NN + n;
        float v = dec_in[bn] + dlt[tid*97 + 32];
        g_dec[bn] = v;
        g_d[bn] = fsigmoid(v);
    }
    if (warp < BSZ) {
        int b = warp;
        size_t bn = (size_t)b*NN + n;
        float p0 = prim_in[bn*64 + lane]      + dlt[b*97 + 33 + lane];
        float p1 = prim_in[bn*64 + lane + 32] + dlt[b*97 + 33 + lane + 32];
        float ss = p0*p0 + p1*p1;
        #pragma unroll
        for (int off = 16; off; off >>= 1) ss += __shfl_xor_sync(0xffffffffu, ss, off);
        float sc = rsqrtf(ss*(1.f/64.f) + 1e-6f);
        g_prim[bn*64 + lane]      = p0*sc;
        g_prim[bn*64 + lane + 32] = p1*sc;
    }
}

// ---------------- state_const / msg_const (register-tiled GEMM) ----------------
__global__ __launch_bounds__(256, 4)
void k_const(const float* __restrict__ sb1, const float* __restrict__ mb1_,
             const float* __restrict__ nid)
{
    __shared__ float xs[64*132];
    const int tid = threadIdx.x;
    const int r0 = blockIdx.x * 64;
    const int which = blockIdx.y;              // 1 = state, 0 = msg
    const float* WC = which ? g_WsC : g_WmC;
    const float* b1 = which ? sb1 : mb1_;
    float* outp     = which ? (float*)g_sconst4 : (float*)g_mconst4;

    for (int i = tid; i < 64*132; i += 256) {
        int rr = i / 132, j = i - rr*132;
        size_t r = (size_t)(r0 + rr);
        int nn_ = (int)(r & (NN-1));
        float v = 0.f;
        if (j < 64)        v = g_prim[r*64 + j];
        else if (j < 128)  v = nid[(size_t)nn_*64 + (j-64)];
        else if (j == 128) v = g_dec[r];
        xs[i] = v;
    }
    __syncthreads();

    const int ty = tid >> 5, tx = tid & 31;
    float acc[8][8];
    #pragma unroll
    for (int i = 0; i < 8; i++)
        #pragma unroll
        for (int u = 0; u < 8; u++) acc[i][u] = 0.f;
    for (int j = 0; j < 129; ++j) {
        float a[8], w[8];
        #pragma unroll
        for (int i = 0; i < 8; i++) a[i] = xs[(ty*8+i)*132 + j];
        #pragma unroll
        for (int u = 0; u < 8; u++) w[u] = __ldg(WC + j*256 + tx + 32*u);
        #pragma unroll
        for (int i = 0; i < 8; i++)
            #pragma unroll
            for (int u = 0; u < 8; u++) acc[i][u] += a[i]*w[u];
    }
    #pragma unroll
    for (int i = 0; i < 8; i++) {
        int r = r0 + ty*8 + i;
        #pragma unroll
        for (int u = 0; u < 8; u++) {
            int c = tx + 32*u;
            outp[(size_t)r*256 + c] = acc[i][u] + __ldg(b1 + c);
        }
    }
}

// ---------------- wide GEMM: C[64x256] = A[64x64] @ W + const, tanh ----------------
// warp = 32 rows x 64 cols (rh = warp>>2 row half, cq = warp&3 col quarter)
// lane: ry = lane>>3 (row octet in half), cx = lane&7 (8-col group in quarter)
__device__ __forceinline__ void gemm_wide(const float* __restrict__ s_x,
                                          float* __restrict__ s_hid,
                                          const float4* __restrict__ W4,
                                          const float4* __restrict__ cstBase,
                                          int tid)
{
    const int w_  = tid >> 5, ln = tid & 31;
    const int rh = w_ >> 2, cq = w_ & 3;
    const int ry = ln >> 3, cx = ln & 7;
    const int rbase = rh*32 + ry*8;
    const int f = cq*16 + cx*2;          // float4 column index (0..63)

    u64 acc[8][4];
    #pragma unroll
    for (int i = 0; i < 8; i++)
        #pragma unroll
        for (int u = 0; u < 4; u++) acc[i][u] = 0ull;

    #pragma unroll 2
    for (int j = 0; j < 64; j += 2) {
        float2 a2[8];
        #pragma unroll
        for (int i = 0; i < 8; i++)
            a2[i] = *(const float2*)&s_x[(rbase+i)*68 + j];
        #pragma unroll
        for (int jj = 0; jj < 2; jj++) {
            const ulonglong2* wr = (const ulonglong2*)(W4 + (size_t)(j+jj)*64);
            ulonglong2 w0 = __ldg(wr + f);
            ulonglong2 w1 = __ldg(wr + f + 1);
            #pragma unroll
            for (int i = 0; i < 8; i++) {
                u64 ap = pack2(jj ? a2[i].y : a2[i].x);
                ffma2(acc[i][0], ap, w0.x);
                ffma2(acc[i][1], ap, w0.y);
                ffma2(acc[i][2], ap, w1.x);
                ffma2(acc[i][3], ap, w1.y);
            }
        }
    }
    const int cbase = cq*64 + cx*8;      // float column index
    #pragma unroll
    for (int i = 0; i < 8; i++) {
        int r = rbase + i;
        float4 c0 = __ldg(cstBase + (size_t)r*64 + f);
        float4 c1 = __ldg(cstBase + (size_t)r*64 + f + 1);
        float2 p0 = unpack2(acc[i][0]), p1 = unpack2(acc[i][1]);
        float2 p2 = unpack2(acc[i][2]), p3 = unpack2(acc[i][3]);
        float4 o0 = make_float4(ftanh(p0.x+c0.x), ftanh(p0.y+c0.y),
                                ftanh(p1.x+c0.z), ftanh(p1.y+c0.w));
        float4 o1 = make_float4(ftanh(p2.x+c1.x), ftanh(p2.y+c1.y),
                                ftanh(p3.x+c1.z), ftanh(p3.y+c1.w));
        *(float4*)&s_hid[r*260 + cbase]     = o0;
        *(float4*)&s_hid[r*260 + cbase + 4] = o1;
    }
}

// ---------------- narrow GEMM: warp = 32 rows x 16 cols, thread = 4r x 4c ----------------
// lane: ry = lane>>2 (row quad), cx = lane&3 (float4 col within quarter)
__device__ __forceinline__ void gemm_narrow(const float* __restrict__ s_hid,
                                            const float4* __restrict__ W4,
                                            int tid, u64 acc[4][2])
{
    const int w_  = tid >> 5, ln = tid & 31;
    const int rh = w_ >> 2, cq = w_ & 3;
    const int ry = ln >> 2, cx = ln & 3;
    const int rbase = rh*32 + ry*4;
    const int fc = cq*4 + cx;            // float4 column index (0..15)

    #pragma unroll
    for (int i = 0; i < 4; i++) { acc[i][0] = 0ull; acc[i][1] = 0ull; }
    #pragma unroll 2
    for (int k = 0; k < 256; k += 4) {
        float4 a4[4];
        #pragma unroll
        for (int i = 0; i < 4; i++)
            a4[i] = *(const float4*)&s_hid[(rbase+i)*260 + k];
        #pragma unroll
        for (int kk = 0; kk < 4; kk++) {
            ulonglong2 w = __ldg((const ulonglong2*)(W4 + (size_t)(k+kk)*16) + fc);
            #pragma unroll
            for (int i = 0; i < 4; i++) {
                float a = (kk == 0) ? a4[i].x : (kk == 1) ? a4[i].y
                        : (kk == 2) ? a4[i].z : a4[i].w;
                u64 ap = pack2(a);
                ffma2(acc[i][0], ap, w.x);
                ffma2(acc[i][1], ap, w.y);
            }
        }
    }
}

// ---------------- fused recurrent step ----------------
// smem: s_hid 64x260 | s_x 64x68 | gather (s_ws 2048 + s_cn 2048) | s_ro 256
#define SHID_OFF 0
#define SX_OFF   (TILE*260)
#define SG_OFF   (TILE*260 + TILE*68)
#define SRO_OFF  (TILE*260 + TILE*68 + 4096)
#define STEP_SMEM ((TILE*260 + TILE*68 + 4096 + 256)*4)

__global__ __launch_bounds__(256, 2)
void k_step(int t, const float* __restrict__ cc, const int* __restrict__ conn,
            const float* __restrict__ nid, const float* __restrict__ sb2,
            const float* __restrict__ mb2, float* __restrict__ out)
{
    extern __shared__ float sm[];
    float* s_hid = sm + SHID_OFF;
    float* s_x   = sm + SX_OFF;
    float* s_ws  = sm + SG_OFF;
    int*   s_cn  = (int*)(s_ws + 2048);
    float* s_ro  = sm + SRO_OFF;

    const int tid = threadIdx.x;
    const int b  = blockIdx.y;
    const int nt = blockIdx.x;
    const int n0 = nt*TILE;
    const int sel = t & 1;

    {
        const float4* c4 = (const float4*)(conn) + (size_t)n0*8;
        const float4* w4 = (const float4*)g_wsig4 + ((size_t)b*NN + n0)*8;
        float4* sc4 = (float4*)s_cn;
        float4* sw4 = (float4*)s_ws;
        #pragma unroll
        for (int i = tid; i < 512; i += 256) { sc4[i] = __ldg(c4 + i); sw4[i] = __ldg(w4 + i); }
    }
    __syncthreads();

    // ---- phase 0: gather (+inject) -> recv in s_x ----
    {
        const int wp_ = tid >> 5, ln = tid & 31;
        const u64* mq = (const u64*)((const float*)g_msg4[sel] + (size_t)b*NN*64);
        #pragma unroll 1
        for (int g = 0; g < 8; ++g) {
            int nl = g*8 + wp_;
            const int*   cp  = s_cn + nl*32;
            const float* wsp = s_ws + nl*32;
            u64 a0 = 0ull, a1 = 0ull;
            #pragma unroll
            for (int k = 0; k < 32; k += 4) {
                int4   id = *(const int4*)(cp + k);
                float4 wt = *(const float4*)(wsp + k);
                ffma2(a0, pack2(wt.x), mq[(size_t)id.x*32 + ln]);
                ffma2(a1, pack2(wt.y), mq[(size_t)id.y*32 + ln]);
                ffma2(a0, pack2(wt.z), mq[(size_t)id.z*32 + ln]);
                ffma2(a1, pack2(wt.w), mq[(size_t)id.w*32 + ln]);
            }
            float2 r0 = unpack2(a0), r1 = unpack2(a1);
            float x0 = r0.x + r1.x, x1 = r0.y + r1.y;
            int n = n0 + nl;
            if ((n & 127) < 4) {
                float2 cv = *(const float2*)(cc + ((size_t)b*TT + t)*2048 + (n>>7)*64 + ln*2);
                x0 += cv.x; x1 += cv.y;
            }
            *(float2*)&s_x[nl*68 + ln*2] = make_float2(x0, x1);
        }
    }
    __syncthreads();

    // ---- phase 1: hid = tanh(recv @ Wsi + state_const) ----
    gemm_wide(s_x, s_hid, g_Wsi4, g_sconst4 + ((size_t)b*NN + n0)*64, tid);
    __syncthreads();

    // ---- phase 2: upd = tanh(hid @ Ws2 + sb2); h = d*h + (1-d)*upd ----
    {
        u64 acc[4][2];
        gemm_narrow(s_hid, g_Ws24, tid, acc);
        const int w_  = tid >> 5, ln = tid & 31;
        const int rh = w_ >> 2, cq = w_ & 3;
        const int ry = ln >> 2, cx = ln & 3;
        const int rbase = rh*32 + ry*4;
        const int fc = cq*4 + cx;
        float4 bb = __ldg((const float4*)sb2 + fc);
        #pragma unroll
        for (int i = 0; i < 4; i++) {
            int r = rbase + i;
            size_t row = (size_t)b*NN + n0 + r;
            float dv = g_d[row];
            float2 p0 = unpack2(acc[i][0]), p1 = unpack2(acc[i][1]);
            float4 hb = g_h4[row*16 + fc];
            float u0 = ftanh(p0.x + bb.x), u1 = ftanh(p0.y + bb.y);
            float u2 = ftanh(p1.x + bb.z), u3 = ftanh(p1.y + bb.w);
            float4 hv = make_float4(dv*hb.x + (1.f-dv)*u0, dv*hb.y + (1.f-dv)*u1,
                                    dv*hb.z + (1.f-dv)*u2, dv*hb.w + (1.f-dv)*u3);
            g_h4[row*16 + fc] = hv;
            *(float4*)&s_x[r*68 + fc*4] = hv;
        }
    }
    __syncthreads();

    // ---- phase 3: mh = tanh(h @ Wmh + msg_const) ----
    gemm_wide(s_x, s_hid, g_Wmh4, g_mconst4 + ((size_t)b*NN + n0)*64, tid);
    __syncthreads();

    // ---- phase 4: msg = tanh(mh @ Wm2 + mb2) + nid; readout ----
    {
        u64 acc[4][2];
        gemm_narrow(s_hid, g_Wm24, tid, acc);
        const int w_  = tid >> 5, ln = tid & 31;
        const int rh = w_ >> 2, cq = w_ & 3;
        const int ry = ln >> 2, cx = ln & 3;
        const int rbase = rh*32 + ry*4;
        const int fc = cq*4 + cx;
        float4 bb = __ldg((const float4*)mb2 + fc);
        float4* msgout = g_msg4[sel^1];
        #pragma unroll
        for (int i = 0; i < 4; i++) {
            int r = rbase + i;
            int n = n0 + r;
            size_t row = (size_t)b*NN + n;
            float2 p0 = unpack2(acc[i][0]), p1 = unpack2(acc[i][1]);
            float4 nv = __ldg((const float4*)nid + (size_t)n*16 + fc);
            float4 mv = make_float4(ftanh(p0.x + bb.x) + nv.x, ftanh(p0.y + bb.y) + nv.y,
                                    ftanh(p1.x + bb.z) + nv.z, ftanh(p1.y + bb.w) + nv.w);
            msgout[row*16 + fc] = mv;
            if ((nt & 1) && r >= 60) *(float4*)&s_ro[(r-60)*64 + fc*4] = mv;
        }
    }
    if (nt & 1) {
        __syncthreads();
        if (tid < 64) {
            float v = 0.25f*(s_ro[tid] + s_ro[64+tid] + s_ro[128+tid] + s_ro[192+tid]);
            out[((size_t)b*TT + t)*2048 + (nt >> 1)*64 + tid] = v;
        }
    }
}

// ---------------- launcher ----------------
extern "C" void kernel_launch(void* const* d_in, const int* in_sizes, int n_in,
                              void* d_out, int out_size)
{
    const float* cc      = (const float*)d_in[0];
    const float* h_in    = (const float*)d_in[1];
    const float* msg_in  = (const float*)d_in[2];
    const float* wconn   = (const float*)d_in[3];
    const float* declog  = (const float*)d_in[4];
    const float* prim_in = (const float*)d_in[5];
    const float* heb     = (const float*)d_in[6];
    const float* sw1     = (const float*)d_in[7];
    const float* sb1     = (const float*)d_in[8];
    const float* sw2     = (const float*)d_in[9];
    const float* sb2     = (const float*)d_in[10];
    const float* mw1     = (const float*)d_in[11];
    const float* mb1     = (const float*)d_in[12];
    const float* mw2     = (const float*)d_in[13];
    const float* mb2     = (const float*)d_in[14];
    const float* modw1   = (const float*)d_in[15];
    const float* modb1   = (const float*)d_in[16];
    const float* modw2   = (const float*)d_in[17];
    const float* modb2   = (const float*)d_in[18];
    const float* nid     = (const float*)d_in[19];
    const int*   conn    = (const int*)d_in[20];
    float* out = (float*)d_out;

    cudaFuncSetAttribute(k_step, cudaFuncAttributeMaxDynamicSharedMemorySize, STEP_SMEM);

    k_init<<<256, 256>>>(h_in, msg_in, sw1, sw2, mw1, mw2);
    k_mod<<<NN, 256>>>(h_in, heb, declog, prim_in, wconn,
                       modw1, modb1, modw2, modb2, nid);
    k_const<<<dim3(512, 2), 256>>>(sb1, mb1, nid);

    for (int t = 0; t < TT; ++t) {
        k_step<<<dim3(NN/TILE, 8), 256, STEP_SMEM>>>(t, cc, conn, nid, sb2, mb2, out);
    }
}

// round 8
// speedup vs baseline: 1.2212x; 1.2212x over previous
#include <cuda_runtime.h>
#include <math.h>

#define NN  4096
#define KK  32
#define DD  64
#define BSZ 8
#define TT  32
#define HSZ 256
#define TILE 64

typedef unsigned long long u64;

// ---------------- persistent device scratch (float4-aligned) ----------------
__device__ float4 g_wsig4[BSZ*NN*KK/4];
__device__ float  g_d[BSZ*NN];
__device__ float  g_dec[BSZ*NN];
__device__ float  g_prim[BSZ*NN*DD];
__device__ float4 g_sconst4[(size_t)BSZ*NN*HSZ/4];
__device__ float4 g_mconst4[(size_t)BSZ*NN*HSZ/4];
__device__ float4 g_h4[BSZ*NN*DD/4];
__device__ float4 g_msg4[2][BSZ*NN*DD/4];
__device__ float4 g_Wsi4[DD*HSZ/4];    // state_w1[:, :64]  -> [j][h]
__device__ float4 g_Ws24[HSZ*DD/4];    // state_w2          -> [h][o]
__device__ float4 g_Wmh4[DD*HSZ/4];    // msg_w1[:, :64]    -> [j][h]
__device__ float4 g_Wm24[HSZ*DD/4];    // msg_w2            -> [h][o]
__device__ float  g_WsC[129*HSZ];      // const-GEMM weights [j][h]
__device__ float  g_WmC[129*HSZ];

// ---------------- fast math + f32x2 helpers ----------------
__device__ __forceinline__ float ftanh(float x) {
    float ax = fabsf(x);
    float e  = __expf(-2.f*ax);
    float t  = __fdividef(1.f - e, 1.f + e);
    return copysignf(t, x);
}
__device__ __forceinline__ float fsigmoid(float x) {
    return __fdividef(1.f, 1.f + __expf(-x));
}
__device__ __forceinline__ u64 pack2(float x) {
    u64 r; unsigned xi = __float_as_uint(x);
    asm("mov.b64 %0, {%1,%1};" : "=l"(r) : "r"(xi));
    return r;
}
__device__ __forceinline__ float2 unpack2(u64 v) {
    unsigned lo, hi;
    asm("mov.b64 {%0,%1}, %2;" : "=r"(lo), "=r"(hi) : "l"(v));
    return make_float2(__uint_as_float(lo), __uint_as_float(hi));
}
__device__ __forceinline__ void ffma2(u64& d, u64 a, u64 b) {
    asm("fma.rn.f32x2 %0, %1, %2, %0;" : "+l"(d) : "l"(a), "l"(b));
}

// ---------------- init: copy state, pack weights ----------------
__global__ void k_init(const float* __restrict__ h_in, const float* __restrict__ msg_in,
                       const float* __restrict__ sw1, const float* __restrict__ sw2,
                       const float* __restrict__ mw1, const float* __restrict__ mw2)
{
    int i0 = blockIdx.x*blockDim.x + threadIdx.x;
    int stride = gridDim.x*blockDim.x;
    float* gh   = (float*)g_h4;
    float* gm0  = (float*)g_msg4[0];
    float* Wsi  = (float*)g_Wsi4;  float* Ws2 = (float*)g_Ws24;
    float* Wmh  = (float*)g_Wmh4;  float* Wm2 = (float*)g_Wm24;
    for (int i = i0; i < BSZ*NN*DD; i += stride) { gh[i] = h_in[i]; gm0[i] = msg_in[i]; }
    for (int i = i0; i < DD*HSZ; i += stride) {
        int j = i >> 8, h = i & 255;
        Wsi[i] = sw1[h*193 + j];
        Wmh[i] = mw1[h*192 + j];
    }
    for (int i = i0; i < HSZ*DD; i += stride) {
        int h = i >> 6, o = i & 63;
        Ws2[i] = sw2[o*256 + h];
        Wm2[i] = mw2[o*256 + h];
    }
    for (int i = i0; i < 129*HSZ; i += stride) {
        int j = i >> 8, h = i & 255;
        g_WsC[i] = (j < 128) ? sw1[h*193 + 64 + j] : sw1[h*193 + 192];
        g_WmC[i] = (j < 128) ? mw1[h*192 + 64 + j] : 0.f;
    }
}

// ---------------- per-neuron modulation MLP ----------------
__global__ void k_mod(const float* __restrict__ h_in, const float* __restrict__ heb,
                      const float* __restrict__ dec_in, const float* __restrict__ prim_in,
                      const float* __restrict__ wconn_in,
                      const float* __restrict__ mw1, const float* __restrict__ mb1,
                      const float* __restrict__ mw2, const float* __restrict__ mb2,
                      const float* __restrict__ nid)
{
    const int n = blockIdx.x;
    const int tid = threadIdx.x;
    const int warp = tid >> 5, lane = tid & 31;
    __shared__ float xs[BSZ*225];
    __shared__ float hid[BSZ*64];
    __shared__ float dlt[BSZ*97];

    for (int i = tid; i < BSZ*225; i += 256) {
        int b = i / 225, j = i - b*225;
        size_t bn = (size_t)b*NN + n;
        float v;
        if (j < 32)        v = heb[bn*32 + j];
        else if (j < 96)   v = h_in[bn*64 + (j-32)];
        else if (j == 96)  v = dec_in[bn];
        else if (j < 161)  v = prim_in[bn*64 + (j-97)];
        else               v = nid[(size_t)n*64 + (j-161)];
        xs[i] = v;
    }
    __syncthreads();

    const float* w1 = mw1 + (size_t)n*64*225;
    for (int hh = warp; hh < 64; hh += 8) {
        float acc[BSZ];
        #pragma unroll
        for (int b = 0; b < BSZ; b++) acc[b] = 0.f;
        for (int j = lane; j < 225; j += 32) {
            float w = w1[hh*225 + j];
            #pragma unroll
            for (int b = 0; b < BSZ; b++) acc[b] += w * xs[b*225 + j];
        }
        #pragma unroll
        for (int off = 16; off; off >>= 1) {
            #pragma unroll
            for (int b = 0; b < BSZ; b++) acc[b] += __shfl_xor_sync(0xffffffffu, acc[b], off);
        }
        if (lane == 0) {
            float bb = mb1[(size_t)n*64 + hh];
            #pragma unroll
            for (int b = 0; b < BSZ; b++) hid[b*64 + hh] = ftanh(acc[b] + bb);
        }
    }
    __syncthreads();

    const float* w2 = mw2 + (size_t)n*64*97;
    for (int o = warp; o < 97; o += 8) {
        float acc[BSZ];
        #pragma unroll
        for (int b = 0; b < BSZ; b++) acc[b] = 0.f;
        #pragma unroll
        for (int j2 = 0; j2 < 2; ++j2) {
            int j = lane + 32*j2;
            float w = w2[(size_t)j*97 + o];
            #pragma unroll
            for (int b = 0; b < BSZ; b++) acc[b] += w * hid[b*64 + j];
        }
        #pragma unroll
        for (int off = 16; off; off >>= 1) {
            #pragma unroll
            for (int b = 0; b < BSZ; b++) acc[b] += __shfl_xor_sync(0xffffffffu, acc[b], off);
        }
        if (lane == 0) {
            float bb = mb2[(size_t)n*97 + o];
            #pragma unroll
            for (int b = 0; b < BSZ; b++) dlt[b*97 + o] = acc[b] + bb;
        }
    }
    __syncthreads();

    float* wsig = (float*)g_wsig4;
    for (int i = tid; i < BSZ*KK; i += 256) {
        int b = i >> 5, k = i & 31;
        size_t bn = (size_t)b*NN + n;
        wsig[bn*32 + k] = fsigmoid(wconn_in[bn*32 + k] + dlt[b*97 + k]);
    }
    if (tid < BSZ) {
        size_t bn = (size_t)tid*NN + n;
        float v = dec_in[bn] + dlt[tid*97 + 32];
        g_dec[bn] = v;
        g_d[bn] = fsigmoid(v);
    }
    if (warp < BSZ) {
        int b = warp;
        size_t bn = (size_t)b*NN + n;
        float p0 = prim_in[bn*64 + lane]      + dlt[b*97 + 33 + lane];
        float p1 = prim_in[bn*64 + lane + 32] + dlt[b*97 + 33 + lane + 32];
        float ss = p0*p0 + p1*p1;
        #pragma unroll
        for (int off = 16; off; off >>= 1) ss += __shfl_xor_sync(0xffffffffu, ss, off);
        float sc = rsqrtf(ss*(1.f/64.f) + 1e-6f);
        g_prim[bn*64 + lane]      = p0*sc;
        g_prim[bn*64 + lane + 32] = p1*sc;
    }
}

// ---------------- state_const / msg_const (register-tiled GEMM) ----------------
__global__ __launch_bounds__(256, 4)
void k_const(const float* __restrict__ sb1, const float* __restrict__ mb1_,
             const float* __restrict__ nid)
{
    __shared__ float xs[64*132];
    const int tid = threadIdx.x;
    const int r0 = blockIdx.x * 64;
    const int which = blockIdx.y;              // 1 = state, 0 = msg
    const float* WC = which ? g_WsC : g_WmC;
    const float* b1 = which ? sb1 : mb1_;
    float* outp     = which ? (float*)g_sconst4 : (float*)g_mconst4;

    for (int i = tid; i < 64*132; i += 256) {
        int rr = i / 132, j = i - rr*132;
        size_t r = (size_t)(r0 + rr);
        int nn_ = (int)(r & (NN-1));
        float v = 0.f;
        if (j < 64)        v = g_prim[r*64 + j];
        else if (j < 128)  v = nid[(size_t)nn_*64 + (j-64)];
        else if (j == 128) v = g_dec[r];
        xs[i] = v;
    }
    __syncthreads();

    const int ty = tid >> 5, tx = tid & 31;
    float acc[8][8];
    #pragma unroll
    for (int i = 0; i < 8; i++)
        #pragma unroll
        for (int u = 0; u < 8; u++) acc[i][u] = 0.f;
    for (int j = 0; j < 129; ++j) {
        float a[8], w[8];
        #pragma unroll
        for (int i = 0; i < 8; i++) a[i] = xs[(ty*8+i)*132 + j];
        #pragma unroll
        for (int u = 0; u < 8; u++) w[u] = __ldg(WC + j*256 + tx + 32*u);
        #pragma unroll
        for (int i = 0; i < 8; i++)
            #pragma unroll
            for (int u = 0; u < 8; u++) acc[i][u] += a[i]*w[u];
    }
    #pragma unroll
    for (int i = 0; i < 8; i++) {
        int r = r0 + ty*8 + i;
        #pragma unroll
        for (int u = 0; u < 8; u++) {
            int c = tx + 32*u;
            outp[(size_t)r*256 + c] = acc[i][u] + __ldg(b1 + c);
        }
    }
}

// ---------------- per-warp wide GEMM: C[8x256] = A[8x64] @ W + const, tanh ----------------
// s_x, s_hid are THIS WARP's private slices. Warp = 8 rows x 256 cols, lane ln -> cols 4ln..4ln+3, 4ln+128..
__device__ __forceinline__ void gemm_wide_warp(const float* s_x, float* s_hid,
                                               const float4* __restrict__ W4,
                                               const float4* __restrict__ cst, // global-row base *64
                                               int ln)
{
    u64 acc[8][4];
    #pragma unroll
    for (int i = 0; i < 8; i++)
        #pragma unroll
        for (int u = 0; u < 4; u++) acc[i][u] = 0ull;

    #pragma unroll 2
    for (int j = 0; j < 64; j += 2) {
        float2 a2[8];
        #pragma unroll
        for (int i = 0; i < 8; i++)
            a2[i] = *(const float2*)&s_x[i*68 + j];
        #pragma unroll
        for (int jj = 0; jj < 2; jj++) {
            const ulonglong2* wr = (const ulonglong2*)(W4 + (size_t)(j+jj)*64);
            ulonglong2 w0 = __ldg(wr + ln);
            ulonglong2 w1 = __ldg(wr + ln + 32);
            #pragma unroll
            for (int i = 0; i < 8; i++) {
                u64 ap = pack2(jj ? a2[i].y : a2[i].x);
                ffma2(acc[i][0], ap, w0.x);
                ffma2(acc[i][1], ap, w0.y);
                ffma2(acc[i][2], ap, w1.x);
                ffma2(acc[i][3], ap, w1.y);
            }
        }
    }
    #pragma unroll
    for (int i = 0; i < 8; i++) {
        float4 c0 = __ldg(cst + (size_t)i*64 + ln);
        float4 c1 = __ldg(cst + (size_t)i*64 + 32 + ln);
        float2 p0 = unpack2(acc[i][0]), p1 = unpack2(acc[i][1]);
        float2 p2 = unpack2(acc[i][2]), p3 = unpack2(acc[i][3]);
        float4 o0 = make_float4(ftanh(p0.x+c0.x), ftanh(p0.y+c0.y),
                                ftanh(p1.x+c0.z), ftanh(p1.y+c0.w));
        float4 o1 = make_float4(ftanh(p2.x+c1.x), ftanh(p2.y+c1.y),
                                ftanh(p3.x+c1.z), ftanh(p3.y+c1.w));
        *(float4*)&s_hid[i*260 + ln*4]       = o0;
        *(float4*)&s_hid[i*260 + 128 + ln*4] = o1;
    }
}

// ---------------- per-warp narrow GEMM: acc[4 rows][2 pairs] += H[8x256] @ W ----------------
// half-warp tz = ln>>4 -> local rows tz*4..+4; tq = ln&15 -> cols 4tq..4tq+3
__device__ __forceinline__ void gemm_narrow_warp(const float* s_hid,
                                                 const float4* __restrict__ W4,
                                                 int ln, u64 acc[4][2])
{
    const int tz = ln >> 4, tq = ln & 15;
    #pragma unroll
    for (int i = 0; i < 4; i++) { acc[i][0] = 0ull; acc[i][1] = 0ull; }
    #pragma unroll 2
    for (int k = 0; k < 256; k += 4) {
        float4 a4[4];
        #pragma unroll
        for (int i = 0; i < 4; i++)
            a4[i] = *(const float4*)&s_hid[(tz*4+i)*260 + k];
        #pragma unroll
        for (int kk = 0; kk < 4; kk++) {
            ulonglong2 w = __ldg((const ulonglong2*)(W4 + (size_t)(k+kk)*16) + tq);
            #pragma unroll
            for (int i = 0; i < 4; i++) {
                float a = (kk == 0) ? a4[i].x : (kk == 1) ? a4[i].y
                        : (kk == 2) ? a4[i].z : a4[i].w;
                u64 ap = pack2(a);
                ffma2(acc[i][0], ap, w.x);
                ffma2(acc[i][1], ap, w.y);
            }
        }
    }
}

// ---------------- fused recurrent step (fully warp-synchronous) ----------------
// Warp w owns tile rows 8w..8w+8 through all phases. No __syncthreads at all.
// smem: per-warp s_hid (8x260) x 8 warps | per-warp s_x (8x68) x 8 warps
#define SHID_WARP (8*260)
#define SX_WARP   (8*68)
#define STEP_SMEM ((8*SHID_WARP + 8*SX_WARP)*4)

__global__ __launch_bounds__(256, 2)
void k_step(int t, const float* __restrict__ cc, const int* __restrict__ conn,
            const float* __restrict__ nid, const float* __restrict__ sb2,
            const float* __restrict__ mb2, float* __restrict__ out)
{
    extern __shared__ float sm[];
    const int tid = threadIdx.x;
    const int w   = tid >> 5, ln = tid & 31;
    float* s_hid = sm + w*SHID_WARP;
    float* s_x   = sm + 8*SHID_WARP + w*SX_WARP;

    const int b  = blockIdx.y;
    const int nt = blockIdx.x;
    const int n0 = nt*TILE;
    const int r0 = w*8;                       // warp's row base within tile
    const int sel = t & 1;
    const size_t growbase = (size_t)b*NN + n0 + r0;   // global row base for this warp

    // ---- phase 0: gather (+inject) -> this warp's 8 rows of s_x ----
    {
        const u64*    mq  = (const u64*)((const float*)g_msg4[sel] + (size_t)b*NN*64);
        const int4*   cn4 = (const int4*)conn;
        const float4* ws4 = (const float4*)g_wsig4;
        #pragma unroll 1
        for (int g = 0; g < 8; ++g) {
            const int n = n0 + r0 + g;
            const size_t cb = (size_t)n*8;
            const size_t wb = ((size_t)b*NN + n)*8;
            u64 a0 = 0ull, a1 = 0ull;
            #pragma unroll
            for (int kq = 0; kq < 8; ++kq) {
                int4   id = __ldg(cn4 + cb + kq);
                float4 wt = __ldg(ws4 + wb + kq);
                ffma2(a0, pack2(wt.x), mq[(size_t)id.x*32 + ln]);
                ffma2(a1, pack2(wt.y), mq[(size_t)id.y*32 + ln]);
                ffma2(a0, pack2(wt.z), mq[(size_t)id.z*32 + ln]);
                ffma2(a1, pack2(wt.w), mq[(size_t)id.w*32 + ln]);
            }
            float2 v0 = unpack2(a0), v1 = unpack2(a1);
            float x0 = v0.x + v1.x, x1 = v0.y + v1.y;
            if ((n & 127) < 4) {
                float2 cv = *(const float2*)(cc + ((size_t)b*TT + t)*2048 + (n>>7)*64 + ln*2);
                x0 += cv.x; x1 += cv.y;
            }
            *(float2*)&s_x[g*68 + ln*2] = make_float2(x0, x1);
        }
    }
    __syncwarp();

    // ---- phase 1: hid = tanh(recv @ Wsi + state_const) ----
    gemm_wide_warp(s_x, s_hid, g_Wsi4, g_sconst4 + growbase*64, ln);
    __syncwarp();

    // ---- phase 2: upd = tanh(hid @ Ws2 + sb2); h = d*h + (1-d)*upd ----
    {
        u64 acc[4][2];
        gemm_narrow_warp(s_hid, g_Ws24, ln, acc);
        const int tz = ln >> 4, tq = ln & 15;
        float4 bb = __ldg((const float4*)sb2 + tq);
        #pragma unroll
        for (int i = 0; i < 4; i++) {
            int rl = tz*4 + i;
            size_t row = growbase + rl;
            float dv = g_d[row];
            float2 p0 = unpack2(acc[i][0]), p1 = unpack2(acc[i][1]);
            float4 hb = g_h4[row*16 + tq];
            float u0 = ftanh(p0.x + bb.x), u1 = ftanh(p0.y + bb.y);
            float u2 = ftanh(p1.x + bb.z), u3 = ftanh(p1.y + bb.w);
            float4 hv = make_float4(dv*hb.x + (1.f-dv)*u0, dv*hb.y + (1.f-dv)*u1,
                                    dv*hb.z + (1.f-dv)*u2, dv*hb.w + (1.f-dv)*u3);
            g_h4[row*16 + tq] = hv;
            *(float4*)&s_x[rl*68 + tq*4] = hv;
        }
    }
    __syncwarp();

    // ---- phase 3: mh = tanh(h @ Wmh + msg_const) ----
    gemm_wide_warp(s_x, s_hid, g_Wmh4, g_mconst4 + growbase*64, ln);
    __syncwarp();

    // ---- phase 4: msg = tanh(mh @ Wm2 + mb2) + nid; in-register readout ----
    {
        u64 acc[4][2];
        gemm_narrow_warp(s_hid, g_Wm24, ln, acc);
        const int tz = ln >> 4, tq = ln & 15;
        float4 bb = __ldg((const float4*)mb2 + tq);
        float4* msgout = g_msg4[sel^1];
        float4 ro = make_float4(0.f, 0.f, 0.f, 0.f);
        #pragma unroll
        for (int i = 0; i < 4; i++) {
            int rl = tz*4 + i;
            int n = n0 + r0 + rl;
            size_t row = growbase + rl;
            float2 p0 = unpack2(acc[i][0]), p1 = unpack2(acc[i][1]);
            float4 nv = __ldg((const float4*)nid + (size_t)n*16 + tq);
            float4 mv = make_float4(ftanh(p0.x + bb.x) + nv.x, ftanh(p0.y + bb.y) + nv.y,
                                    ftanh(p1.x + bb.z) + nv.z, ftanh(p1.y + bb.w) + nv.w);
            msgout[row*16 + tq] = mv;
            ro.x += mv.x; ro.y += mv.y; ro.z += mv.z; ro.w += mv.w;
        }
        // rows 60..63 live in warp 7, half-warp tz=1 -> readout entirely in registers
        if ((nt & 1) && w == 7 && tz == 1) {
            float4 v = make_float4(0.25f*ro.x, 0.25f*ro.y, 0.25f*ro.z, 0.25f*ro.w);
            *(float4*)&out[((size_t)b*TT + t)*2048 + (nt >> 1)*64 + tq*4] = v;
        }
    }
}

// ---------------- launcher ----------------
extern "C" void kernel_launch(void* const* d_in, const int* in_sizes, int n_in,
                              void* d_out, int out_size)
{
    const float* cc      = (const float*)d_in[0];
    const float* h_in    = (const float*)d_in[1];
    const float* msg_in  = (const float*)d_in[2];
    const float* wconn   = (const float*)d_in[3];
    const float* declog  = (const float*)d_in[4];
    const float* prim_in = (const float*)d_in[5];
    const float* heb     = (const float*)d_in[6];
    const float* sw1     = (const float*)d_in[7];
    const float* sb1     = (const float*)d_in[8];
    const float* sw2     = (const float*)d_in[9];
    const float* sb2     = (const float*)d_in[10];
    const float* mw1     = (const float*)d_in[11];
    const float* mb1     = (const float*)d_in[12];
    const float* mw2     = (const float*)d_in[13];
    const float* mb2     = (const float*)d_in[14];
    const float* modw1   = (const float*)d_in[15];
    const float* modb1   = (const float*)d_in[16];
    const float* modw2   = (const float*)d_in[17];
    const float* modb2   = (const float*)d_in[18];
    const float* nid     = (const float*)d_in[19];
    const int*   conn    = (const int*)d_in[20];
    float* out = (float*)d_out;

    cudaFuncSetAttribute(k_step, cudaFuncAttributeMaxDynamicSharedMemorySize, STEP_SMEM);

    k_init<<<256, 256>>>(h_in, msg_in, sw1, sw2, mw1, mw2);
    k_mod<<<NN, 256>>>(h_in, heb, declog, prim_in, wconn,
                       modw1, modb1, modw2, modb2, nid);
    k_const<<<dim3(512, 2), 256>>>(sb1, mb1, nid);

    for (int t = 0; t < TT; ++t) {
        k_step<<<dim3(NN/TILE, 8), 256, STEP_SMEM>>>(t, cc, conn, nid, sb2, mb2, out);
    }
}